// round 12
// baseline (speedup 1.0000x reference)
#include <cuda_runtime.h>
#include <cuda_bf16.h>
#include <cstdint>

#define NS   16
#define NP   2048
#define DIM  64
#define KNN  16
#define QT   128            // queries per CTA
#define NB   128            // points per tile
#define NTILE (NP / NB)     // 16
#define TPB  256            // 8 warps

// ---- bf16 3-split of h + fp32 norms (device scratch; no allocs) ----
__device__ uint4 g_h0[(size_t)NS * NP * DIM / 8];   // 4 MB each (bf16 rows of 64)
__device__ uint4 g_h1[(size_t)NS * NP * DIM / 8];
__device__ uint4 g_h2[(size_t)NS * NP * DIM / 8];
__device__ float g_norm[(size_t)NS * NP];

// B tile smem: 3 splits x 128 rows x 72 bf16 (144B padded stride -> conflict-free)
#define BSTRIDE   144
#define BSPLIT_SZ (NB * BSTRIDE)        // 18432
#define SM_PN     (3 * BSPLIT_SZ)       // 55296: 128 floats
#define SM_TOT    (SM_PN + 512)
// merge scratch overlays B region after last tile: scr_d at 0 (16KB), scr_i at 16384

// mma.sync m16n8k16 row.col f32.bf16.bf16.f32 — baseline PTX, works on sm_103
__device__ __forceinline__ void mma16816(float d[4],
                                         uint32_t a0, uint32_t a1, uint32_t a2, uint32_t a3,
                                         uint32_t b0, uint32_t b1) {
    asm volatile("mma.sync.aligned.m16n8k16.row.col.f32.bf16.bf16.f32 "
        "{%0,%1,%2,%3}, {%4,%5,%6,%7}, {%8,%9}, {%0,%1,%2,%3};"
        : "+f"(d[0]), "+f"(d[1]), "+f"(d[2]), "+f"(d[3])
        : "r"(a0), "r"(a1), "r"(a2), "r"(a3), "r"(b0), "r"(b1));
}

// ldmatrix x4 (baseline PTX sm_75+): matrix m rows from lanes 8m..8m+7
__device__ __forceinline__ void ldmx4(uint32_t r[4], uint32_t addr) {
    asm volatile("ldmatrix.sync.aligned.m8n8.x4.shared.b16 {%0,%1,%2,%3}, [%4];"
        : "=r"(r[0]), "=r"(r[1]), "=r"(r[2]), "=r"(r[3]) : "r"(addr));
}

__device__ __forceinline__ uint32_t smem_u32(const void* p) {
    uint32_t a;
    asm("{ .reg .u64 t; cvta.to.shared.u64 t, %1; cvt.u32.u64 %0, t; }" : "=r"(a) : "l"(p));
    return a;
}

// =================== kernel 0: fp32 -> 3x bf16 splits ======================
__global__ void split_kernel(const float* __restrict__ h)
{
    int i = blockIdx.x * blockDim.x + threadIdx.x;     // handles 4 elems
    if (i >= NS * NP * DIM / 4) return;
    float4 v = reinterpret_cast<const float4*>(h)[i];
    ushort4 s0, s1, s2;
    float f, r;
    #define SPLIT1(comp, fld)                                             \
        f = v.comp;                                                       \
        s0.fld = __bfloat16_as_ushort(__float2bfloat16_rn(f));            \
        r = f - __bfloat162float(__ushort_as_bfloat16(s0.fld));           \
        s1.fld = __bfloat16_as_ushort(__float2bfloat16_rn(r));            \
        r = r - __bfloat162float(__ushort_as_bfloat16(s1.fld));           \
        s2.fld = __bfloat16_as_ushort(__float2bfloat16_rn(r));
    SPLIT1(x, x) SPLIT1(y, y) SPLIT1(z, z) SPLIT1(w, w)
    #undef SPLIT1
    reinterpret_cast<ushort4*>(g_h0)[i] = s0;
    reinterpret_cast<ushort4*>(g_h1)[i] = s1;
    reinterpret_cast<ushort4*>(g_h2)[i] = s2;
}

// =================== kernel 1: exact fp32 norms ============================
__global__ void norm_kernel(const float* __restrict__ h)
{
    int p = blockIdx.x * blockDim.x + threadIdx.x;
    if (p >= NS * NP) return;
    const float4* row = reinterpret_cast<const float4*>(h + (size_t)p * DIM);
    float n = 0.0f;
    #pragma unroll
    for (int i = 0; i < DIM / 4; i++) {
        float4 v = row[i];
        n += v.x * v.x + v.y * v.y + v.z * v.z + v.w * v.w;
    }
    g_norm[p] = n;
}

// top-K insert (strict < keeps earlier index on ties)
#define INS(LD, LI, DIST, IDX)                                           \
    if ((DIST) < LD[KNN - 1]) {                                          \
        float _dd = (DIST); int _di = (IDX);                             \
        _Pragma("unroll")                                                \
        for (int k = 0; k < KNN; k++)                                    \
            if (_dd < LD[k]) {                                           \
                float _td = LD[k]; int _ti = LI[k];                      \
                LD[k] = _dd; LI[k] = _di; _dd = _td; _di = _ti;          \
            }                                                            \
    }

// lexicographic merge from smem scratch
#define MERGE(LD, LI, OFF)                                                  \
    for (int j = 0; j < KNN; j++) {                                         \
        float dj = scr_d[(OFF) + j]; int ij = scr_i[(OFF) + j];             \
        if (dj < LD[KNN - 1] || (dj == LD[KNN - 1] && ij < LI[KNN - 1])) {  \
            float _dd = dj; int _di = ij;                                   \
            _Pragma("unroll")                                               \
            for (int k = 0; k < KNN; k++) {                                 \
                bool sw = (_dd < LD[k]) || (_dd == LD[k] && _di < LI[k]);   \
                if (sw) {                                                   \
                    float _td = LD[k]; int _ti = LI[k];                     \
                    LD[k] = _dd; LI[k] = _di; _dd = _td; _di = _ti;         \
                }                                                           \
            }                                                               \
        }                                                                   \
    }

// =================== kernel 2: HMMA GEMM + fused top-K =====================
__global__ __launch_bounds__(TPB, 1)
void knn_main_kernel(float* __restrict__ out_dist,
                     float* __restrict__ out_dst,
                     float* __restrict__ out_src)
{
    extern __shared__ char smem[];
    float* pnorm = reinterpret_cast<float*>(smem + SM_PN);
    float* scr_d = reinterpret_cast<float*>(smem);            // merge scratch (reuses B)
    int*   scr_i = reinterpret_cast<int*>(smem + 16384);

    const int tid  = threadIdx.x;
    const int warp = tid >> 5;
    const int lane = tid & 31;
    const int g    = lane >> 2;      // group 0..7
    const int tig  = lane & 3;       // thread-in-group
    const int s    = blockIdx.x >> 4;
    const int qt   = blockIdx.x & 15;
    const int arow0 = s * NP + qt * QT;      // global row of first query in CTA

    const int r0 = warp * 16 + g;            // query row (list 0); list 1 = r0 + 8
    const float qn0 = g_norm[arow0 + r0];
    const float qn1 = g_norm[arow0 + r0 + 8];

    // per-lane ldmatrix row base: matrix m = lane>>3 -> {chunk m>>1, half m&1}
    const uint32_t sb = smem_u32(smem);
    const uint32_t ldm_base = sb + (uint32_t)(((lane >> 4) * 8 + (lane & 7)) * BSTRIDE
                                              + ((lane >> 3) & 1) * 16);

    // ---- A fragments from global, resident all kernel: [split][kstep][4] ----
    uint32_t afr[3][4][4];
    {
        const uint32_t* ga[3] = { reinterpret_cast<const uint32_t*>(g_h0),
                                  reinterpret_cast<const uint32_t*>(g_h1),
                                  reinterpret_cast<const uint32_t*>(g_h2) };
        const size_t rA = (size_t)(arow0 + r0) * 32;       // 64 bf16 = 32 words/row
        const size_t rB = (size_t)(arow0 + r0 + 8) * 32;
        #pragma unroll
        for (int sp = 0; sp < 3; sp++)
            #pragma unroll
            for (int ks = 0; ks < 4; ks++) {
                int w0 = tig + 8 * ks;                     // word = cols 2tig+16ks..+1
                afr[sp][ks][0] = ga[sp][rA + w0];
                afr[sp][ks][1] = ga[sp][rB + w0];
                afr[sp][ks][2] = ga[sp][rA + w0 + 4];      // cols +8
                afr[sp][ks][3] = ga[sp][rB + w0 + 4];
            }
    }

    // ---- per-row top-K lists (thread owns rows r0 and r0+8) ----
    float bd0[KNN], bd1[KNN];
    int   bi0[KNN], bi1[KNN];
    #pragma unroll
    for (int k = 0; k < KNN; k++) {
        bd0[k] = 3.4e38f; bd1[k] = 3.4e38f; bi0[k] = 0; bi1[k] = 0;
    }

    const int ta[6] = {0, 0, 1, 1, 0, 2};
    const int tb[6] = {0, 1, 0, 1, 2, 0};

    for (int tile = 0; tile < NTILE; tile++) {
        __syncthreads();   // prior tile's fragment reads complete
        {   // ---- stage B tile: 3 splits, padded conflict-free layout ----
            const int brow0 = s * NP + tile * NB;
            for (int i = tid; i < NB * 8; i += TPB) {      // 8 uint4 per row
                int r = i >> 3, c = i & 7;
                char* dst = smem + (size_t)r * BSTRIDE + c * 16;
                size_t gi = (size_t)(brow0 + r) * 8 + c;
                *reinterpret_cast<uint4*>(dst)                  = g_h0[gi];
                *reinterpret_cast<uint4*>(dst + BSPLIT_SZ)      = g_h1[gi];
                *reinterpret_cast<uint4*>(dst + 2 * BSPLIT_SZ)  = g_h2[gi];
            }
            if (tid < NB) pnorm[tid] = g_norm[brow0 + tid];
        }
        __syncthreads();

        #pragma unroll
        for (int pass = 0; pass < 4; pass++) {             // 32 points per pass
            float d[4][4] = { {0,0,0,0}, {0,0,0,0}, {0,0,0,0}, {0,0,0,0} };
            const uint32_t pb = ldm_base + (uint32_t)(pass * 32 * BSTRIDE);

            #pragma unroll
            for (int ks = 0; ks < 4; ks++) {
                // B frags via ldmatrix.x4: [split][cpair][4]; regs {b0 nc,b1 nc,b0 nc+1,b1 nc+1}
                uint32_t bf[3][2][4];
                #pragma unroll
                for (int sp = 0; sp < 3; sp++)
                    #pragma unroll
                    for (int cp = 0; cp < 2; cp++)
                        ldmx4(bf[sp][cp],
                              pb + (uint32_t)(sp * BSPLIT_SZ + cp * 16 * BSTRIDE + ks * 32));

                #pragma unroll
                for (int t = 0; t < 6; t++)
                    #pragma unroll
                    for (int nc = 0; nc < 4; nc++)
                        mma16816(d[nc],
                                 afr[ta[t]][ks][0], afr[ta[t]][ks][1],
                                 afr[ta[t]][ks][2], afr[ta[t]][ks][3],
                                 bf[tb[t]][nc >> 1][(nc & 1) * 2],
                                 bf[tb[t]][nc >> 1][(nc & 1) * 2 + 1]);
            }

            // ---- fused epilogue: dist + top-K insert (ascending index order) ----
            #pragma unroll
            for (int nc = 0; nc < 4; nc++) {
                int col0 = pass * 32 + nc * 8 + 2 * tig;
                float pn0 = pnorm[col0], pn1 = pnorm[col0 + 1];
                int jb = tile * NB + col0;
                INS(bd0, bi0, fmaf(-2.0f, d[nc][0], qn0 + pn0), jb)
                INS(bd0, bi0, fmaf(-2.0f, d[nc][1], qn0 + pn1), jb + 1)
                INS(bd1, bi1, fmaf(-2.0f, d[nc][2], qn1 + pn0), jb)
                INS(bd1, bi1, fmaf(-2.0f, d[nc][3], qn1 + pn1), jb + 1)
            }
        }
    }

    // =============== cross-thread merge: 4 threads per row ===================
    __syncthreads();   // B region now reusable as scratch

    const int key  = (warp * 8 + g) * 2;        // two slots per (warp,g)
    // round 1: tig 1 -> slot 0, tig 3 -> slot 1
    if (tig & 1) {
        int base = (key + (tig >> 1)) * 32;
        #pragma unroll
        for (int k = 0; k < KNN; k++) {
            scr_d[base + k]      = bd0[k]; scr_i[base + k]      = bi0[k];
            scr_d[base + 16 + k] = bd1[k]; scr_i[base + 16 + k] = bi1[k];
        }
    }
    __syncwarp();
    if (!(tig & 1)) {
        int base = (key + (tig >> 1)) * 32;
        MERGE(bd0, bi0, base)
        MERGE(bd1, bi1, base + 16)
    }
    __syncwarp();
    // round 2: tig 2 -> slot 0; tig 0 merges
    if (tig == 2) {
        int base = key * 32;
        #pragma unroll
        for (int k = 0; k < KNN; k++) {
            scr_d[base + k]      = bd0[k]; scr_i[base + k]      = bi0[k];
            scr_d[base + 16 + k] = bd1[k]; scr_i[base + 16 + k] = bi1[k];
        }
    }
    __syncwarp();
    if (tig == 0) {
        int base = key * 32;
        MERGE(bd0, bi0, base)
        MERGE(bd1, bi1, base + 16)

        const float offs = (float)(s * NP);
        const int   q0   = arow0 + r0;         // global row ids
        const int   q1   = q0 + 8;
        size_t ob0 = (size_t)q0 * KNN, ob1 = (size_t)q1 * KNN;
        #pragma unroll
        for (int k = 0; k < KNN; k++) {
            out_dist[ob0 + k] = bd0[k];
            out_dst [ob0 + k] = (float)bi0[k] + offs;
            out_src [ob0 + k] = (float)q0;
            out_dist[ob1 + k] = bd1[k];
            out_dst [ob1 + k] = (float)bi1[k] + offs;
            out_src [ob1 + k] = (float)q1;
        }
    }
}

extern "C" void kernel_launch(void* const* d_in, const int* in_sizes, int n_in,
                              void* d_out, int out_size)
{
    const float* h = (const float*)d_in[0];

    float* out      = (float*)d_out;
    const size_t nE = (size_t)NS * NP * KNN;
    float* out_dist = out;
    float* out_dst  = out + nE;
    float* out_src  = out + 2 * nE;

    split_kernel<<<(NS * NP * DIM / 4 + 255) / 256, 256>>>(h);
    norm_kernel<<<(NS * NP + 127) / 128, 128>>>(h);

    cudaFuncSetAttribute(knn_main_kernel,
                         cudaFuncAttributeMaxDynamicSharedMemorySize, SM_TOT);
    knn_main_kernel<<<NS * (NP / QT), TPB, SM_TOT>>>(out_dist, out_dst, out_src);
}

// round 14
// speedup vs baseline: 1.6005x; 1.6005x over previous
#include <cuda_runtime.h>
#include <cuda_bf16.h>
#include <cstdint>

#define NS   16
#define NP   2048
#define DIM  64
#define KNN  16
#define QT   128            // queries per CTA
#define NB   128            // points per tile
#define NTILE (NP / NB)     // 16
#define TPB  256            // 8 warps

// ---- bf16 2-split of h + fp32 norms (device scratch; no allocs) ----
__device__ uint4 g_h0[(size_t)NS * NP * DIM / 8];   // 4 MB each (bf16 rows of 64)
__device__ uint4 g_h1[(size_t)NS * NP * DIM / 8];
__device__ float g_norm[(size_t)NS * NP];

// B tile smem: 2 splits x 128 rows x 72 bf16 (144B padded stride -> conflict-free)
#define BSTRIDE   144
#define BSPLIT_SZ (NB * BSTRIDE)        // 18432
#define SM_PN     (2 * BSPLIT_SZ)       // 36864: 128 floats
#define SM_TOT    (SM_PN + 512)
// merge scratch overlays B region after last tile: scr_d at 0 (16KB), scr_i at 16384

// mma.sync m16n8k16 row.col f32.bf16.bf16.f32 — baseline PTX, works on sm_103
__device__ __forceinline__ void mma16816(float d[4],
                                         uint32_t a0, uint32_t a1, uint32_t a2, uint32_t a3,
                                         uint32_t b0, uint32_t b1) {
    asm volatile("mma.sync.aligned.m16n8k16.row.col.f32.bf16.bf16.f32 "
        "{%0,%1,%2,%3}, {%4,%5,%6,%7}, {%8,%9}, {%0,%1,%2,%3};"
        : "+f"(d[0]), "+f"(d[1]), "+f"(d[2]), "+f"(d[3])
        : "r"(a0), "r"(a1), "r"(a2), "r"(a3), "r"(b0), "r"(b1));
}

// ldmatrix x4 (baseline PTX sm_75+)
__device__ __forceinline__ void ldmx4(uint32_t r[4], uint32_t addr) {
    asm volatile("ldmatrix.sync.aligned.m8n8.x4.shared.b16 {%0,%1,%2,%3}, [%4];"
        : "=r"(r[0]), "=r"(r[1]), "=r"(r[2]), "=r"(r[3]) : "r"(addr));
}

__device__ __forceinline__ uint32_t smem_u32(const void* p) {
    uint32_t a;
    asm("{ .reg .u64 t; cvta.to.shared.u64 t, %1; cvt.u32.u64 %0, t; }" : "=r"(a) : "l"(p));
    return a;
}

// =================== kernel 0: fp32 -> 2x bf16 splits ======================
__global__ void split_kernel(const float* __restrict__ h)
{
    int i = blockIdx.x * blockDim.x + threadIdx.x;     // handles 4 elems
    if (i >= NS * NP * DIM / 4) return;
    float4 v = reinterpret_cast<const float4*>(h)[i];
    ushort4 s0, s1;
    float f, r;
    #define SPLIT1(comp, fld)                                             \
        f = v.comp;                                                       \
        s0.fld = __bfloat16_as_ushort(__float2bfloat16_rn(f));            \
        r = f - __bfloat162float(__ushort_as_bfloat16(s0.fld));           \
        s1.fld = __bfloat16_as_ushort(__float2bfloat16_rn(r));
    SPLIT1(x, x) SPLIT1(y, y) SPLIT1(z, z) SPLIT1(w, w)
    #undef SPLIT1
    reinterpret_cast<ushort4*>(g_h0)[i] = s0;
    reinterpret_cast<ushort4*>(g_h1)[i] = s1;
}

// =================== kernel 1: exact fp32 norms ============================
__global__ void norm_kernel(const float* __restrict__ h)
{
    int p = blockIdx.x * blockDim.x + threadIdx.x;
    if (p >= NS * NP) return;
    const float4* row = reinterpret_cast<const float4*>(h + (size_t)p * DIM);
    float n = 0.0f;
    #pragma unroll
    for (int i = 0; i < DIM / 4; i++) {
        float4 v = row[i];
        n += v.x * v.x + v.y * v.y + v.z * v.z + v.w * v.w;
    }
    g_norm[p] = n;
}

// top-K insert (strict < keeps earlier index on ties)
#define INS(LD, LI, DIST, IDX)                                           \
    if ((DIST) < LD[KNN - 1]) {                                          \
        float _dd = (DIST); int _di = (IDX);                             \
        _Pragma("unroll")                                                \
        for (int k = 0; k < KNN; k++)                                    \
            if (_dd < LD[k]) {                                           \
                float _td = LD[k]; int _ti = LI[k];                      \
                LD[k] = _dd; LI[k] = _di; _dd = _td; _di = _ti;          \
            }                                                            \
    }

// lexicographic merge from smem scratch
#define MERGE(LD, LI, OFF)                                                  \
    for (int j = 0; j < KNN; j++) {                                         \
        float dj = scr_d[(OFF) + j]; int ij = scr_i[(OFF) + j];             \
        if (dj < LD[KNN - 1] || (dj == LD[KNN - 1] && ij < LI[KNN - 1])) {  \
            float _dd = dj; int _di = ij;                                   \
            _Pragma("unroll")                                               \
            for (int k = 0; k < KNN; k++) {                                 \
                bool sw = (_dd < LD[k]) || (_dd == LD[k] && _di < LI[k]);   \
                if (sw) {                                                   \
                    float _td = LD[k]; int _ti = LI[k];                     \
                    LD[k] = _dd; LI[k] = _di; _dd = _td; _di = _ti;         \
                }                                                           \
            }                                                               \
        }                                                                   \
    }

// =================== kernel 2: HMMA GEMM + fused top-K =====================
__global__ __launch_bounds__(TPB, 1)
void knn_main_kernel(float* __restrict__ out_dist,
                     float* __restrict__ out_dst,
                     float* __restrict__ out_src)
{
    extern __shared__ char smem[];
    float* pnorm = reinterpret_cast<float*>(smem + SM_PN);
    float* scr_d = reinterpret_cast<float*>(smem);            // merge scratch (reuses B)
    int*   scr_i = reinterpret_cast<int*>(smem + 16384);

    const int tid  = threadIdx.x;
    const int warp = tid >> 5;
    const int lane = tid & 31;
    const int g    = lane >> 2;      // group 0..7
    const int tig  = lane & 3;       // thread-in-group
    const int s    = blockIdx.x >> 4;
    const int qt   = blockIdx.x & 15;
    const int arow0 = s * NP + qt * QT;      // global row of first query in CTA

    const int r0 = warp * 16 + g;            // query row (list 0); list 1 = r0 + 8
    const float qn0 = g_norm[arow0 + r0];
    const float qn1 = g_norm[arow0 + r0 + 8];

    // per-lane ldmatrix row base: matrix m = lane>>3 -> {chunk m>>1, half m&1}
    const uint32_t sb = smem_u32(smem);
    const uint32_t ldm_base = sb + (uint32_t)(((lane >> 4) * 8 + (lane & 7)) * BSTRIDE
                                              + ((lane >> 3) & 1) * 16);

    // ---- A fragments from global, resident all kernel: [split][kstep][4] ----
    uint32_t afr[2][4][4];
    {
        const uint32_t* ga[2] = { reinterpret_cast<const uint32_t*>(g_h0),
                                  reinterpret_cast<const uint32_t*>(g_h1) };
        const size_t rA = (size_t)(arow0 + r0) * 32;       // 64 bf16 = 32 words/row
        const size_t rB = (size_t)(arow0 + r0 + 8) * 32;
        #pragma unroll
        for (int sp = 0; sp < 2; sp++)
            #pragma unroll
            for (int ks = 0; ks < 4; ks++) {
                int w0 = tig + 8 * ks;                     // word = cols 2tig+16ks..+1
                afr[sp][ks][0] = ga[sp][rA + w0];
                afr[sp][ks][1] = ga[sp][rB + w0];
                afr[sp][ks][2] = ga[sp][rA + w0 + 4];      // cols +8
                afr[sp][ks][3] = ga[sp][rB + w0 + 4];
            }
    }

    // ---- per-row top-K lists (thread owns rows r0 and r0+8) ----
    float bd0[KNN], bd1[KNN];
    int   bi0[KNN], bi1[KNN];
    #pragma unroll
    for (int k = 0; k < KNN; k++) {
        bd0[k] = 3.4e38f; bd1[k] = 3.4e38f; bi0[k] = 0; bi1[k] = 0;
    }

    // 2-split, 3 terms: a0b0, a0b1, a1b0 (a1b1 ~ 2^-18 — negligible)
    const int ta[3] = {0, 0, 1};
    const int tb[3] = {0, 1, 0};

    for (int tile = 0; tile < NTILE; tile++) {
        __syncthreads();   // prior tile's fragment reads complete
        {   // ---- stage B tile: 2 splits, padded conflict-free layout ----
            const int brow0 = s * NP + tile * NB;
            for (int i = tid; i < NB * 8; i += TPB) {      // 8 uint4 per row
                int r = i >> 3, c = i & 7;
                char* dst = smem + (size_t)r * BSTRIDE + c * 16;
                size_t gi = (size_t)(brow0 + r) * 8 + c;
                *reinterpret_cast<uint4*>(dst)             = g_h0[gi];
                *reinterpret_cast<uint4*>(dst + BSPLIT_SZ) = g_h1[gi];
            }
            if (tid < NB) pnorm[tid] = g_norm[brow0 + tid];
        }
        __syncthreads();

        #pragma unroll
        for (int pass = 0; pass < 4; pass++) {             // 32 points per pass
            float d[4][4] = { {0,0,0,0}, {0,0,0,0}, {0,0,0,0}, {0,0,0,0} };
            const uint32_t pb = ldm_base + (uint32_t)(pass * 32 * BSTRIDE);

            #pragma unroll
            for (int ks = 0; ks < 4; ks++) {
                // B frags via ldmatrix.x4: [split][cpair][4]; regs {b0 nc,b1 nc,b0 nc+1,b1 nc+1}
                uint32_t bf[2][2][4];
                #pragma unroll
                for (int sp = 0; sp < 2; sp++)
                    #pragma unroll
                    for (int cp = 0; cp < 2; cp++)
                        ldmx4(bf[sp][cp],
                              pb + (uint32_t)(sp * BSPLIT_SZ + cp * 16 * BSTRIDE + ks * 32));

                #pragma unroll
                for (int t = 0; t < 3; t++)
                    #pragma unroll
                    for (int nc = 0; nc < 4; nc++)
                        mma16816(d[nc],
                                 afr[ta[t]][ks][0], afr[ta[t]][ks][1],
                                 afr[ta[t]][ks][2], afr[ta[t]][ks][3],
                                 bf[tb[t]][nc >> 1][(nc & 1) * 2],
                                 bf[tb[t]][nc >> 1][(nc & 1) * 2 + 1]);
            }

            // ---- fused epilogue: dist + top-K insert (ascending index order) ----
            #pragma unroll
            for (int nc = 0; nc < 4; nc++) {
                int col0 = pass * 32 + nc * 8 + 2 * tig;
                float pn0 = pnorm[col0], pn1 = pnorm[col0 + 1];
                int jb = tile * NB + col0;
                INS(bd0, bi0, fmaf(-2.0f, d[nc][0], qn0 + pn0), jb)
                INS(bd0, bi0, fmaf(-2.0f, d[nc][1], qn0 + pn1), jb + 1)
                INS(bd1, bi1, fmaf(-2.0f, d[nc][2], qn1 + pn0), jb)
                INS(bd1, bi1, fmaf(-2.0f, d[nc][3], qn1 + pn1), jb + 1)
            }
        }
    }

    // =============== cross-thread merge: 4 threads per row ===================
    __syncthreads();   // B region now reusable as scratch

    const int key  = (warp * 8 + g) * 2;        // two slots per (warp,g)
    // round 1: tig 1 -> slot 0, tig 3 -> slot 1
    if (tig & 1) {
        int base = (key + (tig >> 1)) * 32;
        #pragma unroll
        for (int k = 0; k < KNN; k++) {
            scr_d[base + k]      = bd0[k]; scr_i[base + k]      = bi0[k];
            scr_d[base + 16 + k] = bd1[k]; scr_i[base + 16 + k] = bi1[k];
        }
    }
    __syncwarp();
    if (!(tig & 1)) {
        int base = (key + (tig >> 1)) * 32;
        MERGE(bd0, bi0, base)
        MERGE(bd1, bi1, base + 16)
    }
    __syncwarp();
    // round 2: tig 2 -> slot 0; tig 0 merges
    if (tig == 2) {
        int base = key * 32;
        #pragma unroll
        for (int k = 0; k < KNN; k++) {
            scr_d[base + k]      = bd0[k]; scr_i[base + k]      = bi0[k];
            scr_d[base + 16 + k] = bd1[k]; scr_i[base + 16 + k] = bi1[k];
        }
    }
    __syncwarp();
    if (tig == 0) {
        int base = key * 32;
        MERGE(bd0, bi0, base)
        MERGE(bd1, bi1, base + 16)

        const float offs = (float)(s * NP);
        const int   q0   = arow0 + r0;         // global row ids
        const int   q1   = q0 + 8;
        size_t ob0 = (size_t)q0 * KNN, ob1 = (size_t)q1 * KNN;
        #pragma unroll
        for (int k = 0; k < KNN; k++) {
            out_dist[ob0 + k] = bd0[k];
            out_dst [ob0 + k] = (float)bi0[k] + offs;
            out_src [ob0 + k] = (float)q0;
            out_dist[ob1 + k] = bd1[k];
            out_dst [ob1 + k] = (float)bi1[k] + offs;
            out_src [ob1 + k] = (float)q1;
        }
    }
}

extern "C" void kernel_launch(void* const* d_in, const int* in_sizes, int n_in,
                              void* d_out, int out_size)
{
    const float* h = (const float*)d_in[0];

    float* out      = (float*)d_out;
    const size_t nE = (size_t)NS * NP * KNN;
    float* out_dist = out;
    float* out_dst  = out + nE;
    float* out_src  = out + 2 * nE;

    split_kernel<<<(NS * NP * DIM / 4 + 255) / 256, 256>>>(h);
    norm_kernel<<<(NS * NP + 127) / 128, 128>>>(h);

    cudaFuncSetAttribute(knn_main_kernel,
                         cudaFuncAttributeMaxDynamicSharedMemorySize, SM_TOT);
    knn_main_kernel<<<NS * (NP / QT), TPB, SM_TOT>>>(out_dist, out_dst, out_src);
}

// round 17
// speedup vs baseline: 3.3846x; 2.1147x over previous
#include <cuda_runtime.h>
#include <cuda_bf16.h>
#include <cstdint>

#define NS   16
#define NP   2048
#define DIM  64
#define KNN  16
#define QT   128            // queries per CTA
#define NB   128            // points per tile
#define NTILE (NP / NB)     // 16
#define TPB  256            // 8 warps

// ---- bf16 2-split of h + fp32 norms (device scratch; no allocs) ----
__device__ uint4 g_h0[(size_t)NS * NP * DIM / 8];   // 4 MB each (bf16 rows of 64)
__device__ uint4 g_h1[(size_t)NS * NP * DIM / 8];
__device__ float g_norm[(size_t)NS * NP];

// B tile smem: 2 splits x 128 rows x 72 bf16 (144B padded stride -> conflict-free)
#define BSTRIDE   144
#define BSPLIT_SZ (NB * BSTRIDE)        // 18432
#define SM_PN     (2 * BSPLIT_SZ)       // 36864: 128 floats
#define SM_TOT    (SM_PN + 512)
// merge scratch overlays B region: scr_d at 0 (16KB), scr_i at 16384 (16KB)

// mma.sync m16n8k16 row.col f32.bf16.bf16.f32 — baseline PTX, works on sm_103
__device__ __forceinline__ void mma16816(float d[4],
                                         uint32_t a0, uint32_t a1, uint32_t a2, uint32_t a3,
                                         uint32_t b0, uint32_t b1) {
    asm volatile("mma.sync.aligned.m16n8k16.row.col.f32.bf16.bf16.f32 "
        "{%0,%1,%2,%3}, {%4,%5,%6,%7}, {%8,%9}, {%0,%1,%2,%3};"
        : "+f"(d[0]), "+f"(d[1]), "+f"(d[2]), "+f"(d[3])
        : "r"(a0), "r"(a1), "r"(a2), "r"(a3), "r"(b0), "r"(b1));
}

// ldmatrix x4 (baseline PTX sm_75+)
__device__ __forceinline__ void ldmx4(uint32_t r[4], uint32_t addr) {
    asm volatile("ldmatrix.sync.aligned.m8n8.x4.shared.b16 {%0,%1,%2,%3}, [%4];"
        : "=r"(r[0]), "=r"(r[1]), "=r"(r[2]), "=r"(r[3]) : "r"(addr));
}

__device__ __forceinline__ uint32_t smem_u32(const void* p) {
    uint32_t a;
    asm("{ .reg .u64 t; cvta.to.shared.u64 t, %1; cvt.u32.u64 %0, t; }" : "=r"(a) : "l"(p));
    return a;
}

// pack: 23-bit fixed-point distance (quantum 1/16384, clamp 510) | 9-bit local code
__device__ __forceinline__ uint32_t pack_key(float dist, uint32_t lc) {
    float dc = fminf(fmaxf(dist, 0.0f), 510.0f);
    uint32_t q = __float2uint_rn(dc * 16384.0f);      // <= 8355840 < 2^23
    return (q << 9) | lc;
}

// =================== kernel 0: prep (split + norm fused) ===================
__global__ void prep_kernel(const float* __restrict__ h)
{
    int i = blockIdx.x * blockDim.x + threadIdx.x;     // one float4 per thread
    if (i >= NS * NP * DIM / 4) return;
    float4 v = reinterpret_cast<const float4*>(h)[i];
    ushort4 s0, s1;
    float f, r;
    #define SPLIT1(comp, fld)                                             \
        f = v.comp;                                                       \
        s0.fld = __bfloat16_as_ushort(__float2bfloat16_rn(f));            \
        r = f - __bfloat162float(__ushort_as_bfloat16(s0.fld));           \
        s1.fld = __bfloat16_as_ushort(__float2bfloat16_rn(r));
    SPLIT1(x, x) SPLIT1(y, y) SPLIT1(z, z) SPLIT1(w, w)
    #undef SPLIT1
    reinterpret_cast<ushort4*>(g_h0)[i] = s0;
    reinterpret_cast<ushort4*>(g_h1)[i] = s1;

    // norm: 16 consecutive threads cover one row (64 floats)
    float part = v.x * v.x + v.y * v.y + v.z * v.z + v.w * v.w;
    #pragma unroll
    for (int off = 8; off >= 1; off >>= 1)
        part += __shfl_xor_sync(0xFFFFFFFFu, part, off, 16);
    if ((i & 15) == 0) g_norm[i >> 4] = part;
}

// top-K insert on packed keys: 2 IMNMX per step, single-compare guard
#define INSK(L, KEY)                                                     \
    if ((KEY) < L[KNN - 1]) {                                            \
        uint32_t _k = (KEY);                                             \
        _Pragma("unroll")                                                \
        for (int k = 0; k < KNN; k++) {                                  \
            uint32_t _mx = max(_k, L[k]);                                \
            L[k] = min(_k, L[k]);                                        \
            _k = _mx;                                                    \
        }                                                                \
    }

// lexicographic (dist, idx) merge from smem scratch — exact cross-thread ties
#define MERGE(LD, LI, OFF)                                                  \
    for (int j = 0; j < KNN; j++) {                                         \
        float dj = scr_d[(OFF) + j]; int ij = scr_i[(OFF) + j];             \
        if (dj < LD[KNN - 1] || (dj == LD[KNN - 1] && ij < LI[KNN - 1])) {  \
            float _dd = dj; int _di = ij;                                   \
            _Pragma("unroll")                                               \
            for (int k = 0; k < KNN; k++) {                                 \
                bool sw = (_dd < LD[k]) || (_dd == LD[k] && _di < LI[k]);   \
                if (sw) {                                                   \
                    float _td = LD[k]; int _ti = LI[k];                     \
                    LD[k] = _dd; LI[k] = _di; _dd = _td; _di = _ti;         \
                }                                                           \
            }                                                               \
        }                                                                   \
    }

// =================== kernel 1: HMMA GEMM + fused top-K =====================
__global__ __launch_bounds__(TPB, 1)
void knn_main_kernel(float* __restrict__ out_dist,
                     float* __restrict__ out_dst,
                     float* __restrict__ out_src)
{
    extern __shared__ char smem[];
    float*    pnorm = reinterpret_cast<float*>(smem + SM_PN);
    float*    scr_d = reinterpret_cast<float*>(smem);         // merge scratch (reuses B)
    int*      scr_i = reinterpret_cast<int*>(smem + 16384);

    const int tid  = threadIdx.x;
    const int warp = tid >> 5;
    const int lane = tid & 31;
    const int g    = lane >> 2;      // group 0..7
    const int tig  = lane & 3;       // thread-in-group
    const int s    = blockIdx.x >> 4;
    const int qt   = blockIdx.x & 15;
    const int arow0 = s * NP + qt * QT;      // global row of first query in CTA

    const int r0 = warp * 16 + g;            // query row (list 0); list 1 = r0 + 8
    const float qn0 = g_norm[arow0 + r0];
    const float qn1 = g_norm[arow0 + r0 + 8];

    // per-lane ldmatrix row base: matrix m = lane>>3 -> {cpair m>>1, half m&1}
    const uint32_t sb = smem_u32(smem);
    const uint32_t ldm_base = sb + (uint32_t)(((lane >> 4) * 8 + (lane & 7)) * BSTRIDE
                                              + ((lane >> 3) & 1) * 16);

    // ---- A fragments from global, resident all kernel: [split][kstep][4] ----
    uint32_t afr[2][4][4];
    {
        const uint32_t* ga[2] = { reinterpret_cast<const uint32_t*>(g_h0),
                                  reinterpret_cast<const uint32_t*>(g_h1) };
        const size_t rA = (size_t)(arow0 + r0) * 32;       // 64 bf16 = 32 words/row
        const size_t rB = (size_t)(arow0 + r0 + 8) * 32;
        #pragma unroll
        for (int sp = 0; sp < 2; sp++)
            #pragma unroll
            for (int ks = 0; ks < 4; ks++) {
                int w0 = tig + 8 * ks;                     // word = cols 2tig+16ks..+1
                afr[sp][ks][0] = ga[sp][rA + w0];
                afr[sp][ks][1] = ga[sp][rB + w0];
                afr[sp][ks][2] = ga[sp][rA + w0 + 4];      // cols +8
                afr[sp][ks][3] = ga[sp][rB + w0 + 4];
            }
    }

    // ---- per-row top-K packed-key lists ----
    uint32_t l0[KNN], l1[KNN];
    #pragma unroll
    for (int k = 0; k < KNN; k++) { l0[k] = 0xFFFFFFFFu; l1[k] = 0xFFFFFFFFu; }

    for (int tile = 0; tile < NTILE; tile++) {
        __syncthreads();   // prior tile's fragment reads complete
        {   // ---- stage B tile: 2 splits, padded conflict-free layout ----
            const int brow0 = s * NP + tile * NB;
            for (int i = tid; i < NB * 8; i += TPB) {      // 8 uint4 per row
                int r = i >> 3, c = i & 7;
                char* dst = smem + (size_t)r * BSTRIDE + c * 16;
                size_t gi = (size_t)(brow0 + r) * 8 + c;
                *reinterpret_cast<uint4*>(dst)             = g_h0[gi];
                *reinterpret_cast<uint4*>(dst + BSPLIT_SZ) = g_h1[gi];
            }
            if (tid < NB) pnorm[tid] = g_norm[brow0 + tid];
        }
        __syncthreads();

        #pragma unroll
        for (int pass = 0; pass < 4; pass++) {             // 32 points per pass
            float d[4][4] = { {0,0,0,0}, {0,0,0,0}, {0,0,0,0}, {0,0,0,0} };
            const uint32_t pb = ldm_base + (uint32_t)(pass * 32 * BSTRIDE);

            #pragma unroll
            for (int ks = 0; ks < 4; ks++) {
                // B frags via ldmatrix.x4: [split][cpair][4]
                uint32_t bf[2][2][4];
                #pragma unroll
                for (int sp = 0; sp < 2; sp++)
                    #pragma unroll
                    for (int cp = 0; cp < 2; cp++)
                        ldmx4(bf[sp][cp],
                              pb + (uint32_t)(sp * BSPLIT_SZ + cp * 16 * BSTRIDE + ks * 32));

                // 4 terms: a0b0, a0b1, a1b0, a1b1 (full 2-split product)
                #pragma unroll
                for (int t = 0; t < 4; t++) {
                    const int tA = t >> 1, tB = t & 1;
                    #pragma unroll
                    for (int nc = 0; nc < 4; nc++)
                        mma16816(d[nc],
                                 afr[tA][ks][0], afr[tA][ks][1],
                                 afr[tA][ks][2], afr[tA][ks][3],
                                 bf[tB][nc >> 1][(nc & 1) * 2],
                                 bf[tB][nc >> 1][(nc & 1) * 2 + 1]);
                }
            }

            // ---- fused epilogue: dist -> 23-bit fixed key | 9-bit local code ----
            #pragma unroll
            for (int nc = 0; nc < 4; nc++) {
                int col0 = pass * 32 + nc * 8 + 2 * tig;
                float pn0 = pnorm[col0], pn1 = pnorm[col0 + 1];
                uint32_t lc0 = (uint32_t)((tile << 5) | (pass << 3) | (nc << 1));
                uint32_t k00 = pack_key(fmaf(-2.0f, d[nc][0], qn0 + pn0), lc0);
                uint32_t k01 = pack_key(fmaf(-2.0f, d[nc][1], qn0 + pn1), lc0 + 1);
                uint32_t k10 = pack_key(fmaf(-2.0f, d[nc][2], qn1 + pn0), lc0);
                uint32_t k11 = pack_key(fmaf(-2.0f, d[nc][3], qn1 + pn1), lc0 + 1);
                INSK(l0, k00)
                INSK(l0, k01)
                INSK(l1, k10)
                INSK(l1, k11)
            }
        }
    }

    // =============== cross-thread merge: 4 threads per row ===================
    __syncthreads();   // B region now reusable as scratch

    // unpack this thread's lists to exact (quantized dist, GLOBAL idx)
    float bd0[KNN], bd1[KNN];
    int   bi0[KNN], bi1[KNN];
    #pragma unroll
    for (int k = 0; k < KNN; k++) {
        uint32_t lc = l0[k] & 0x1FFu;
        bd0[k] = (float)(l0[k] >> 9) * (1.0f / 16384.0f);
        bi0[k] = (int)(((lc >> 5) << 7) + (((lc >> 3) & 3u) << 5)
                       + (((lc >> 1) & 3u) << 3) + 2 * tig + (lc & 1u));
        lc = l1[k] & 0x1FFu;
        bd1[k] = (float)(l1[k] >> 9) * (1.0f / 16384.0f);
        bi1[k] = (int)(((lc >> 5) << 7) + (((lc >> 3) & 3u) << 5)
                       + (((lc >> 1) & 3u) << 3) + 2 * tig + (lc & 1u));
    }

    const int key = (warp * 8 + g) * 2;        // two slots per (warp,g)
    // round 1: tig 1 -> slot 0, tig 3 -> slot 1
    if (tig & 1) {
        int base = (key + (tig >> 1)) * 32;
        #pragma unroll
        for (int k = 0; k < KNN; k++) {
            scr_d[base + k]      = bd0[k]; scr_i[base + k]      = bi0[k];
            scr_d[base + 16 + k] = bd1[k]; scr_i[base + 16 + k] = bi1[k];
        }
    }
    __syncwarp();
    if (!(tig & 1)) {
        int base = (key + (tig >> 1)) * 32;
        MERGE(bd0, bi0, base)
        MERGE(bd1, bi1, base + 16)
    }
    __syncwarp();
    // round 2: tig 2 -> slot 0; tig 0 merges
    if (tig == 2) {
        int base = key * 32;
        #pragma unroll
        for (int k = 0; k < KNN; k++) {
            scr_d[base + k]      = bd0[k]; scr_i[base + k]      = bi0[k];
            scr_d[base + 16 + k] = bd1[k]; scr_i[base + 16 + k] = bi1[k];
        }
    }
    __syncwarp();
    if (tig == 0) {
        int base = key * 32;
        MERGE(bd0, bi0, base)
        MERGE(bd1, bi1, base + 16)

        const float offs = (float)(s * NP);
        const int   q0   = arow0 + r0;         // global row ids
        const int   q1   = q0 + 8;
        size_t ob0 = (size_t)q0 * KNN, ob1 = (size_t)q1 * KNN;
        #pragma unroll
        for (int k = 0; k < KNN; k++) {
            out_dist[ob0 + k] = bd0[k];
            out_dst [ob0 + k] = (float)bi0[k] + offs;
            out_src [ob0 + k] = (float)q0;
            out_dist[ob1 + k] = bd1[k];
            out_dst [ob1 + k] = (float)bi1[k] + offs;
            out_src [ob1 + k] = (float)q1;
        }
    }
}

extern "C" void kernel_launch(void* const* d_in, const int* in_sizes, int n_in,
                              void* d_out, int out_size)
{
    const float* h = (const float*)d_in[0];

    float* out      = (float*)d_out;
    const size_t nE = (size_t)NS * NP * KNN;
    float* out_dist = out;
    float* out_dst  = out + nE;
    float* out_src  = out + 2 * nE;

    prep_kernel<<<(NS * NP * DIM / 4 + 255) / 256, 256>>>(h);

    cudaFuncSetAttribute(knn_main_kernel,
                         cudaFuncAttributeMaxDynamicSharedMemorySize, SM_TOT);
    knn_main_kernel<<<NS * (NP / QT), TPB, SM_TOT>>>(out_dist, out_dst, out_src);
}